// round 14
// baseline (speedup 1.0000x reference)
#include <cuda_runtime.h>
#include <cuda_fp16.h>
#include <cstdint>

#define SLOT_BYTES 40960
#define OFF_B      0                   // 2 slots x 40KB ring
#define OFF_FW     81920
#define OFF_BF     (OFF_FW + 512)
#define OFF_W1W    (OFF_BF + 512)
#define OFF_W1B    (OFF_W1W + 512)
#define OFF_XW     (OFF_W1B + 512)
#define OFF_XB     (OFF_XW + 512)
#define OFF_UB     (OFF_XB + 512)
#define OFF_MB     (OFF_UB + 512)
#define OFF_RED    (OFF_MB + 32)       // 128 rows x 4 float2 = 4KB
#define SMEM_TOTAL (OFF_RED + 4096)

// g_B: fp16 B-fragment images, 14 steps (layout identical to R9/R10):
//  steps 0-7 fourier combo: word offset p*10240; steps 8..13: 81920 + (s-8)*8192
__device__ __align__(16) unsigned g_B[126976];
__device__ float g_freqw[128];

__device__ __forceinline__ uint32_t smem_u32(const void* p) {
    uint32_t a;
    asm("{ .reg .u64 t; cvta.to.shared.u64 t, %1; cvt.u32.u64 %0, t; }" : "=r"(a) : "l"(p));
    return a;
}
__device__ __forceinline__ bool elect_one() {
    uint32_t p;
    asm volatile("{\n\t.reg .pred P;\n\telect.sync _|P, 0xFFFFFFFF;\n\tselp.b32 %0,1,0,P;\n\t}" : "=r"(p));
    return p != 0;
}
__device__ __forceinline__ void mbar_wait(uint32_t mbar, uint32_t phase) {
    uint32_t done = 0;
    while (!done) {
        asm volatile(
            "{\n\t.reg .pred P;\n\tmbarrier.try_wait.parity.acquire.cta.shared::cta.b64 P, [%1], %2, 0x989680;\n\tselp.b32 %0,1,0,P;\n\t}"
            : "=r"(done) : "r"(mbar), "r"(phase) : "memory");
    }
}
__device__ __forceinline__ unsigned packh2(float a, float b) {
    __half2 h = __floats2half2_rn(a, b);
    return *reinterpret_cast<unsigned*>(&h);
}
__device__ __forceinline__ float tanh_fast(float x) {
    float r;
    asm("tanh.approx.f32 %0, %1;" : "=f"(r) : "f"(x));
    return r;
}
__device__ __forceinline__ void hmma(float* c, const unsigned* a, unsigned b0, unsigned b1) {
    asm volatile("mma.sync.aligned.m16n8k16.row.col.f32.f16.f16.f32 "
                 "{%0,%1,%2,%3}, {%4,%5,%6,%7}, {%8,%9}, {%0,%1,%2,%3};"
                 : "+f"(c[0]), "+f"(c[1]), "+f"(c[2]), "+f"(c[3])
                 : "r"(a[0]), "r"(a[1]), "r"(a[2]), "r"(a[3]), "r"(b0), "r"(b1));
}
// 4 n-tiles (32 cols) for one m16 A fragment
__device__ __forceinline__ void mma4(float* acc, const unsigned* a, const uint4* bq) {
    hmma(acc + 0,  a, bq[0].x, bq[0].y);
    hmma(acc + 4,  a, bq[0].z, bq[0].w);
    hmma(acc + 8,  a, bq[1].x, bq[1].y);
    hmma(acc + 12, a, bq[1].z, bq[1].w);
}
__device__ __forceinline__ float bsp(float s) {
    float t2 = fabsf(s - 2.0f);
    float r1 = fmaf((0.5f * t2 - 1.0f) * t2, t2, 2.0f / 3.0f);
    float am = fmaxf(2.0f - t2, 0.0f);
    float r2 = am * am * am * (1.0f / 6.0f);
    return t2 < 1.0f ? r1 : r2;
}
// pack fragment pair (a0: rows 0,+8 ; a1: rows +16,+24) from V[ai*4 + r]
__device__ __forceinline__ void pack_frag(const float* V, unsigned* a0, unsigned* a1) {
    a0[0] = packh2(V[0],  V[4]);  a0[1] = packh2(V[1],  V[5]);
    a0[2] = packh2(V[8],  V[12]); a0[3] = packh2(V[9],  V[13]);
    a1[0] = packh2(V[2],  V[6]);  a1[1] = packh2(V[3],  V[7]);
    a1[2] = packh2(V[10], V[14]); a1[3] = packh2(V[11], V[15]);
}

// ---------------- prep (layout identical to R9/R10) ----------------
__global__ void prep_kernel(const float* __restrict__ fourier_weight,
                            const float* __restrict__ base_weight,
                            const float* __restrict__ spline_weight,
                            const float* __restrict__ freq_theta)
{
    int idx = blockIdx.x * blockDim.x + threadIdx.x;
    int stride = gridDim.x * blockDim.x;
    if (idx < 128) {
        float sp = log1pf(expf(freq_theta[idx]));
        g_freqw[idx] = exp10f(-(9.0f * idx) / 127.0f) * (sp + 1e-6f);
    }
    for (int w = idx; w < 126976; w += stride) {
        float w0, w1;
        if (w < 81920) {
            int f = w / 10240;
            int within = w - f * 10240;
            int ks   = within >> 10;
            int c4   = (within >> 7) & 7;
            int lane = (within >> 2) & 31;
            int q    = within & 3;
            int nt = 2 * c4 + (q >> 1);
            int n  = nt * 8 + (lane >> 2);
            int kl = (lane & 3) * 2 + (q & 1) * 8;
            int d  = 16 * f + kl;
            int s  = ks & 1, kh = ks >> 1;
            w0 = fourier_weight[((size_t)(s * 128 + n) * 128 + d)     * 5 + kh];
            w1 = fourier_weight[((size_t)(s * 128 + n) * 128 + d + 1) * 5 + kh];
        } else {
            int base = (w < 122880) ? (w & 8191) : (w - 122880);
            int ks   = base >> 10;
            int c4   = (base >> 7) & 7;
            int lane = (base >> 2) & 31;
            int q    = base & 3;
            int nt = 2 * c4 + (q >> 1);
            int n  = nt * 8 + (lane >> 2);
            int k0 = 16 * ks + (lane & 3) * 2 + (q & 1) * 8;
            if (w < 90112) {
                w0 = base_weight[n * 128 + k0];
                w1 = base_weight[n * 128 + k0 + 1];
            } else if (w < 98304) {
                int dl = k0 & 15, m = k0 >> 4;
                w0 = spline_weight[((size_t)n * 128 + dl)     * 8 + m];
                w1 = spline_weight[((size_t)n * 128 + dl + 1) * 8 + m];
            } else if (w < 122880) {
                int bb = (w - 98304) >> 13;
                int mslot = k0 >> 5, dl = k0 & 31;
                int d = 16 + bb * 32 + dl, m = mslot + 2;
                w0 = spline_weight[((size_t)n * 128 + d)     * 8 + m];
                w1 = spline_weight[((size_t)n * 128 + d + 1) * 8 + m];
            } else {
                int mslot = k0 >> 4, dl = k0 & 15;
                int d = 112 + dl, m = mslot + 2;
                w0 = spline_weight[((size_t)n * 128 + d)     * 8 + m];
                w1 = spline_weight[((size_t)n * 128 + d + 1) * 8 + m];
            }
        }
        g_B[w] = packh2(w0, w1);
    }
}

// ---------------- main: 512 threads, 16 warps (4M x 4N), warp tile m32n32 ----------------
__global__ void __launch_bounds__(512, 1)
main_kernel(const float* __restrict__ ts,
            const float* __restrict__ bias_fourier,
            const float* __restrict__ w1w,
            const float* __restrict__ w1b,
            const float* __restrict__ ln_w,
            const float* __restrict__ ln_b,
            const float* __restrict__ scale_w,
            float* __restrict__ out)
{
    extern __shared__ __align__(16) unsigned char smem[];
    const int tid = threadIdx.x, wid = tid >> 5, lane = tid & 31;
    const int wm = wid >> 2, wn2 = wid & 3;
    const int row0 = blockIdx.x * 128;

    float* s_fw  = (float*)(smem + OFF_FW);
    float* s_bf  = (float*)(smem + OFF_BF);
    float* s_w1w = (float*)(smem + OFF_W1W);
    float* s_w1b = (float*)(smem + OFF_W1B);
    float* s_xw  = (float*)(smem + OFF_XW);
    float* s_ub  = (float*)(smem + OFF_UB);
    float2* red  = (float2*)(smem + OFF_RED);
    uint32_t sb = smem_u32(smem);
    uint32_t fullb[2]  = { sb + OFF_MB,      sb + OFF_MB + 8 };
    uint32_t emptyb[2] = { sb + OFF_MB + 16, sb + OFF_MB + 24 };

    if (tid < 128) {
        float fw = g_freqw[tid];
        float wv = w1w[tid], wb = w1b[tid];
        s_fw[tid]  = fw;
        s_bf[tid]  = bias_fourier[tid];
        s_w1w[tid] = wv;
        s_w1b[tid] = wb;
        s_xw[tid]  = 2.5f * wv;
        ((float*)(smem + OFF_XB))[tid] = fmaf(wb, 2.5f, 5.5f);
        s_ub[tid]  = fmaf(wb, 2.5f, 0.5f);
    }
    if (tid == 0) {
        asm volatile("mbarrier.init.shared.b64 [%0], 1;"  :: "r"(fullb[0]) : "memory");
        asm volatile("mbarrier.init.shared.b64 [%0], 1;"  :: "r"(fullb[1]) : "memory");
        asm volatile("mbarrier.init.shared.b64 [%0], 16;" :: "r"(emptyb[0]) : "memory");
        asm volatile("mbarrier.init.shared.b64 [%0], 16;" :: "r"(emptyb[1]) : "memory");
    }
    __syncthreads();
    if (tid == 0) {
        asm volatile("fence.proxy.async.shared::cta;" ::: "memory");
#pragma unroll
        for (int p = 0; p < 2; p++) {
            asm volatile("mbarrier.arrive.expect_tx.shared.b64 _, [%0], %1;"
                         :: "r"(fullb[p]), "r"((uint32_t)SLOT_BYTES) : "memory");
            asm volatile("cp.async.bulk.shared::cluster.global.mbarrier::complete_tx::bytes [%0], [%1], %2, [%3];"
                         :: "r"(sb + OFF_B + p * SLOT_BYTES),
                            "l"((const void*)(g_B + (size_t)p * 10240)),
                            "r"((uint32_t)SLOT_BYTES), "r"(fullb[p]) : "memory");
        }
    }

    const int r0 = 32 * wm + (lane >> 2);     // rows r0, +8, +16, +24
    const int c2 = (lane & 3) * 2;
    const int boff0 = wn2 * 1024 + lane * 16; // 2 c4-groups per N-warp
    float tr[4];
    tr[0] = ts[row0 + r0];
    tr[1] = ts[row0 + r0 + 8];
    tr[2] = ts[row0 + r0 + 16];
    tr[3] = ts[row0 + r0 + 24];

    int phF[2] = {0, 0};
    int phE[2] = {0, 0};

#define STEP_WOFF(s_)  ((s_) < 8 ? (uint32_t)(s_) * 10240u : 81920u + (uint32_t)((s_) - 8) * 8192u)
#define STEP_BYTES(s_) ((s_) < 8 ? 40960u : ((s_) == 13 ? 16384u : 32768u))

#define PRODUCE(pp)                                                                          \
    if (elect_one()) asm volatile("mbarrier.arrive.shared::cta.b64 _, [%0];" :: "r"(emptyb[(pp) & 1]) : "memory"); \
    if (tid == 0 && (pp) + 2 <= 13) {                                                        \
        mbar_wait(emptyb[(pp) & 1], (uint32_t)phE[(pp) & 1]);                                \
        phE[(pp) & 1] ^= 1;                                                                  \
        int s_ = (pp) + 2;                                                                   \
        asm volatile("mbarrier.arrive.expect_tx.shared.b64 _, [%0], %1;"                     \
                     :: "r"(fullb[(pp) & 1]), "r"(STEP_BYTES(s_)) : "memory");               \
        asm volatile("cp.async.bulk.shared::cluster.global.mbarrier::complete_tx::bytes [%0], [%1], %2, [%3];" \
                     :: "r"(sb + OFF_B + ((pp) & 1) * SLOT_BYTES),                           \
                        "l"((const void*)(g_B + STEP_WOFF(s_))),                             \
                        "r"(STEP_BYTES(s_)), "r"(fullb[(pp) & 1]) : "memory");               \
    }

#define LOADB2(bq, bp, ksv)                                                                  \
    {                                                                                        \
        (bq)[0] = *(const uint4*)((bp) + (ksv) * 4096 + boff0);                              \
        (bq)[1] = *(const uint4*)((bp) + (ksv) * 4096 + boff0 + 512);                        \
    }

    float accF0[16], accF1[16];
#pragma unroll
    for (int i = 0; i < 16; i++) { accF0[i] = 0.0f; accF1[i] = 0.0f; }

    // ======== fourier steps 0..7 : angle-addition recurrence, m32n32 ========
    for (int p = 0; p < 8; p++) {
        int b = p & 1;
        mbar_wait(fullb[b], (uint32_t)phF[b]); phF[b] ^= 1;
        const unsigned char* bp = smem + OFF_B + b * SLOT_BYTES;
        float c1[16], s1[16], ck[16], sk[16];
        uint4 bb[2][2];
        LOADB2(bb[0], bp, 0);
#pragma unroll
        for (int ai = 0; ai < 4; ai++) {
            int d = 16 * p + c2 + (ai & 1) + (ai >> 1) * 8;
            float fw = s_fw[d], bf = s_bf[d];
#pragma unroll
            for (int r = 0; r < 4; r++) {
                __sincosf(fmaf(tr[r], fw, bf), &s1[ai * 4 + r], &c1[ai * 4 + r]);
                ck[ai * 4 + r] = c1[ai * 4 + r];
                sk[ai * 4 + r] = s1[ai * 4 + r];
            }
        }
#pragma unroll
        for (int ks = 0; ks < 10; ks++) {
            if (ks + 1 < 10) LOADB2(bb[(ks + 1) & 1], bp, ks + 1);
            if (ks >= 2 && (ks & 1) == 0) {
#pragma unroll
                for (int i = 0; i < 16; i++) {
                    float cn = fmaf(ck[i], c1[i], -(sk[i] * s1[i]));
                    float sn = fmaf(sk[i], c1[i],  ck[i] * s1[i]);
                    ck[i] = cn; sk[i] = sn;
                }
            }
            unsigned a0[4], a1[4];
            pack_frag((ks & 1) ? sk : ck, a0, a1);
            mma4(accF0, a0, bb[ks & 1]);
            mma4(accF1, a1, bb[ks & 1]);
        }
        PRODUCE(p)
    }

    float accS0[16], accS1[16];
#pragma unroll
    for (int i = 0; i < 16; i++) { accS0[i] = 0.0f; accS1[i] = 0.0f; }

    // ======== step 8 : tanh (MUFU.TANH) ========
    {
        mbar_wait(fullb[0], (uint32_t)phF[0]); phF[0] ^= 1;
        const unsigned char* bp = smem + OFF_B;
        uint4 bb[2][2];
        LOADB2(bb[0], bp, 0);
#pragma unroll
        for (int ks = 0; ks < 8; ks++) {
            if (ks + 1 < 8) LOADB2(bb[(ks + 1) & 1], bp, ks + 1);
            float V[16];
#pragma unroll
            for (int ai = 0; ai < 4; ai++) {
                int d = 16 * ks + c2 + (ai & 1) + (ai >> 1) * 8;
                float wv = s_w1w[d], wb = s_w1b[d];
#pragma unroll
                for (int r = 0; r < 4; r++)
                    V[ai * 4 + r] = tanh_fast(fmaf(tr[r], wv, wb));
            }
            unsigned a0[4], a1[4];
            pack_frag(V, a0, a1);
            mma4(accS0, a0, bb[ks & 1]);
            mma4(accS1, a1, bb[ks & 1]);
        }
        PRODUCE(8)
    }

    // ======== step 9 : spline g0 full m-major (general bsp) ========
    {
        mbar_wait(fullb[1], (uint32_t)phF[1]); phF[1] ^= 1;
        const unsigned char* bp = smem + OFF_B + SLOT_BYTES;
        uint4 bb[2][2];
        LOADB2(bb[0], bp, 0);
        float xi[16];
#pragma unroll
        for (int ai = 0; ai < 4; ai++) {
            int d = c2 + (ai & 1) + (ai >> 1) * 8;
            float xw = s_xw[d];
            float xb = ((float*)(smem + OFF_XB))[d];
#pragma unroll
            for (int r = 0; r < 4; r++)
                xi[ai * 4 + r] = fmaf(tr[r], xw, xb);
        }
#pragma unroll
        for (int ks = 0; ks < 8; ks++) {
            if (ks + 1 < 8) LOADB2(bb[(ks + 1) & 1], bp, ks + 1);
            const float fks = (float)ks;
            float V[16];
#pragma unroll
            for (int i = 0; i < 16; i++) V[i] = bsp(xi[i] - fks);
            unsigned a0[4], a1[4];
            pack_frag(V, a0, a1);
            mma4(accS0, a0, bb[ks & 1]);
            mma4(accS1, a1, bb[ks & 1]);
        }
        PRODUCE(9)
    }

    // ---- sp32 helpers: interior dims, ii==5 exact, bases m=2..5 ----
#define SP_BASES(ai, dval, uB0, uB1, uB2, uB3)                                               \
    {                                                                                        \
        float xw = s_xw[dval], ub = s_ub[dval];                                              \
        _Pragma("unroll")                                                                    \
        for (int r = 0; r < 4; r++) {                                                        \
            float u = fmaf(tr[r], xw, ub);                                                   \
            float um = 1.0f - u, u2 = u * u;                                                 \
            uB0[(ai)*4+r] = um * um * (um * (1.0f/6.0f));                                    \
            uB3[(ai)*4+r] = u2 * (u * (1.0f/6.0f));                                          \
            uB1[(ai)*4+r] = fmaf(u2, fmaf(u, 0.5f, -1.0f), 2.0f/3.0f);                       \
            uB2[(ai)*4+r] = 1.0f - uB0[(ai)*4+r] - uB1[(ai)*4+r] - uB3[(ai)*4+r];            \
        }                                                                                    \
    }
#define SP_MMA2(Barr, bqv)                                                                   \
    {                                                                                        \
        unsigned a0[4], a1[4];                                                               \
        pack_frag(Barr, a0, a1);                                                             \
        mma4(accS0, a0, bqv);                                                                \
        mma4(accS1, a1, bqv);                                                                \
    }
#define SP32_CHUNK(bp, bbk)                                                                  \
    {                                                                                        \
        _Pragma("unroll")                                                                    \
        for (int par = 0; par < 2; par++) {                                                  \
            float B0[16], B1[16], B2[16], B3[16];                                            \
            uint4 q0[2], q1[2];                                                              \
            LOADB2(q0, bp, par);                                                             \
            _Pragma("unroll")                                                                \
            for (int ai = 0; ai < 4; ai++) {                                                 \
                int d = 16 + (bbk) * 32 + par * 16 + c2 + (ai & 1) + (ai >> 1) * 8;          \
                SP_BASES(ai, d, B0, B1, B2, B3)                                              \
            }                                                                                \
            LOADB2(q1, bp, 2 + par);                                                         \
            SP_MMA2(B0, q0)                                                                  \
            LOADB2(q0, bp, 4 + par);                                                         \
            SP_MMA2(B1, q1)                                                                  \
            LOADB2(q1, bp, 6 + par);                                                         \
            SP_MMA2(B2, q0)                                                                  \
            SP_MMA2(B3, q1)                                                                  \
        }                                                                                    \
    }

    // ======== steps 10..12 : sp32 blocks 0..2 ========
    {
        mbar_wait(fullb[0], (uint32_t)phF[0]); phF[0] ^= 1;
        SP32_CHUNK(smem + OFF_B, 0)
        PRODUCE(10)
    }
    {
        mbar_wait(fullb[1], (uint32_t)phF[1]); phF[1] ^= 1;
        SP32_CHUNK(smem + OFF_B + SLOT_BYTES, 1)
        PRODUCE(11)
    }
    {
        mbar_wait(fullb[0], (uint32_t)phF[0]); phF[0] ^= 1;
        SP32_CHUNK(smem + OFF_B, 2)
        PRODUCE(12)
    }
    // ======== step 13 : sp-half (d 112..127, K=64) ========
    {
        mbar_wait(fullb[1], (uint32_t)phF[1]); phF[1] ^= 1;
        const unsigned char* bp = smem + OFF_B + SLOT_BYTES;
        float B0[16], B1[16], B2[16], B3[16];
        uint4 q0[2], q1[2];
        LOADB2(q0, bp, 0);
#pragma unroll
        for (int ai = 0; ai < 4; ai++) {
            int d = 112 + c2 + (ai & 1) + (ai >> 1) * 8;
            SP_BASES(ai, d, B0, B1, B2, B3)
        }
        LOADB2(q1, bp, 1);
        SP_MMA2(B0, q0)
        LOADB2(q0, bp, 2);
        SP_MMA2(B1, q1)
        LOADB2(q1, bp, 3);
        SP_MMA2(B2, q0)
        SP_MMA2(B3, q1)
    }

    // ---------------- epilogue: register-resident LN, 4 rows/thread ----------------
#pragma unroll
    for (int i = 0; i < 16; i++) {
        accF0[i] *= 0.5f; accF1[i] *= 0.5f; accS0[i] *= 0.5f; accS1[i] *= 0.5f;
    }

    float s[4] = {0, 0, 0, 0}, q[4] = {0, 0, 0, 0};
#pragma unroll
    for (int t = 0; t < 4; t++) {
#pragma unroll
        for (int j = 0; j < 2; j++) {
            float a0 = accF0[4 * t + j],     b0 = accS0[4 * t + j];
            float a1 = accF0[4 * t + 2 + j], b1 = accS0[4 * t + 2 + j];
            float a2 = accF1[4 * t + j],     b2 = accS1[4 * t + j];
            float a3 = accF1[4 * t + 2 + j], b3 = accS1[4 * t + 2 + j];
            s[0] += a0 + b0; q[0] += a0 * a0 + b0 * b0;
            s[1] += a1 + b1; q[1] += a1 * a1 + b1 * b1;
            s[2] += a2 + b2; q[2] += a2 * a2 + b2 * b2;
            s[3] += a3 + b3; q[3] += a3 * a3 + b3 * b3;
        }
    }
#pragma unroll
    for (int off = 1; off <= 2; off <<= 1) {
#pragma unroll
        for (int r = 0; r < 4; r++) {
            s[r] += __shfl_xor_sync(0xffffffffu, s[r], off);
            q[r] += __shfl_xor_sync(0xffffffffu, q[r], off);
        }
    }
    if ((lane & 3) == 0) {
#pragma unroll
        for (int r = 0; r < 4; r++)
            red[(r0 + 8 * r) * 4 + wn2] = make_float2(s[r], q[r]);
    }
    __syncthreads();
    float mu[4], rs[4];
#pragma unroll
    for (int r = 0; r < 4; r++) {
        float2 r0v = red[(r0 + 8 * r) * 4];
        float2 r1v = red[(r0 + 8 * r) * 4 + 1];
        float2 r2v = red[(r0 + 8 * r) * 4 + 2];
        float2 r3v = red[(r0 + 8 * r) * 4 + 3];
        float sum = r0v.x + r1v.x + r2v.x + r3v.x;
        float sq  = r0v.y + r1v.y + r2v.y + r3v.y;
        mu[r] = sum * (1.0f / 256.0f);
        rs[r] = rsqrtf(sq * (1.0f / 256.0f) - mu[r] * mu[r] + 1e-5f);
    }
    float* op[4];
#pragma unroll
    for (int r = 0; r < 4; r++) op[r] = out + (size_t)(row0 + r0 + 8 * r) * 256;

#pragma unroll
    for (int t = 0; t < 4; t++) {
        int col = wn2 * 32 + t * 8 + c2;
        float2 lw = __ldg((const float2*)&ln_w[col]);
        float2 lb = __ldg((const float2*)&ln_b[col]);
        float2 sw = __ldg((const float2*)&scale_w[col]);
        *(float2*)&op[0][col] = make_float2(
            ((accF0[4 * t]     - mu[0]) * rs[0] * lw.x + lb.x) * sw.x,
            ((accF0[4 * t + 1] - mu[0]) * rs[0] * lw.y + lb.y) * sw.y);
        *(float2*)&op[1][col] = make_float2(
            ((accF0[4 * t + 2] - mu[1]) * rs[1] * lw.x + lb.x) * sw.x,
            ((accF0[4 * t + 3] - mu[1]) * rs[1] * lw.y + lb.y) * sw.y);
        *(float2*)&op[2][col] = make_float2(
            ((accF1[4 * t]     - mu[2]) * rs[2] * lw.x + lb.x) * sw.x,
            ((accF1[4 * t + 1] - mu[2]) * rs[2] * lw.y + lb.y) * sw.y);
        *(float2*)&op[3][col] = make_float2(
            ((accF1[4 * t + 2] - mu[3]) * rs[3] * lw.x + lb.x) * sw.x,
            ((accF1[4 * t + 3] - mu[3]) * rs[3] * lw.y + lb.y) * sw.y);
        int cs = col + 128;
        lw = __ldg((const float2*)&ln_w[cs]);
        lb = __ldg((const float2*)&ln_b[cs]);
        sw = __ldg((const float2*)&scale_w[cs]);
        *(float2*)&op[0][cs] = make_float2(
            ((accS0[4 * t]     - mu[0]) * rs[0] * lw.x + lb.x) * sw.x,
            ((accS0[4 * t + 1] - mu[0]) * rs[0] * lw.y + lb.y) * sw.y);
        *(float2*)&op[1][cs] = make_float2(
            ((accS0[4 * t + 2] - mu[1]) * rs[1] * lw.x + lb.x) * sw.x,
            ((accS0[4 * t + 3] - mu[1]) * rs[1] * lw.y + lb.y) * sw.y);
        *(float2*)&op[2][cs] = make_float2(
            ((accS1[4 * t]     - mu[2]) * rs[2] * lw.x + lb.x) * sw.x,
            ((accS1[4 * t + 1] - mu[2]) * rs[2] * lw.y + lb.y) * sw.y);
        *(float2*)&op[3][cs] = make_float2(
            ((accS1[4 * t + 2] - mu[3]) * rs[3] * lw.x + lb.x) * sw.x,
            ((accS1[4 * t + 3] - mu[3]) * rs[3] * lw.y + lb.y) * sw.y);
    }
}

extern "C" void kernel_launch(void* const* d_in, const int* in_sizes, int n_in,
                              void* d_out, int out_size)
{
    const float* timestamps   = (const float*)d_in[0];
    const float* freq_theta   = (const float*)d_in[1];
    const float* bias_fourier = (const float*)d_in[2];
    const float* fourier_w    = (const float*)d_in[3];
    const float* w1w          = (const float*)d_in[4];
    const float* w1b          = (const float*)d_in[5];
    const float* base_w       = (const float*)d_in[6];
    const float* spline_w     = (const float*)d_in[7];
    const float* scale_w      = (const float*)d_in[8];
    const float* ln_w         = (const float*)d_in[9];
    const float* ln_b         = (const float*)d_in[10];
    float* out = (float*)d_out;

    int nrows = in_sizes[0];   // 16384
    cudaFuncSetAttribute(main_kernel, cudaFuncAttributeMaxDynamicSharedMemorySize, SMEM_TOTAL);
    prep_kernel<<<152, 256>>>(fourier_w, base_w, spline_w, freq_theta);
    main_kernel<<<nrows / 128, 512, SMEM_TOTAL>>>(
        timestamps, bias_fourier, w1w, w1b, ln_w, ln_b, scale_w, out);
}

// round 15
// speedup vs baseline: 1.2901x; 1.2901x over previous
#include <cuda_runtime.h>
#include <cuda_fp16.h>
#include <cstdint>

// ---------------- table config ----------------
// G=512 knots, tau_j = (j-1)/509, j=0..511; t in [0,1) -> u = t*509+1, j=floor(u) in [1,509]
#define GKNOTS 512
#define HINV   509.0f

// tprep smem: single 40KB B slot + params
#define OFF_B    0
#define OFF_FW   40960
#define OFF_BF   (OFF_FW + 512)
#define OFF_W1W  (OFF_BF + 512)
#define OFF_W1B  (OFF_W1W + 512)
#define OFF_XW   (OFF_W1B + 512)
#define OFF_XB   (OFF_XW + 512)
#define OFF_UB   (OFF_XB + 512)
#define OFF_MB   (OFF_UB + 512)
#define TP_SMEM  (OFF_MB + 32)

// g_B: fp16 B-fragment images, 14 steps (layout identical to R9/R10)
__device__ __align__(16) unsigned g_B[126976];
__device__ float g_freqw[128];
__device__ float g_part[14 * GKNOTS * 128];          // per-step partial tiles (3.7MB)
__device__ __align__(16) __half g_T16[GKNOTS * 256]; // final table

__device__ __forceinline__ uint32_t smem_u32(const void* p) {
    uint32_t a;
    asm("{ .reg .u64 t; cvta.to.shared.u64 t, %1; cvt.u32.u64 %0, t; }" : "=r"(a) : "l"(p));
    return a;
}
__device__ __forceinline__ void mbar_wait(uint32_t mbar, uint32_t phase) {
    uint32_t done = 0;
    while (!done) {
        asm volatile(
            "{\n\t.reg .pred P;\n\tmbarrier.try_wait.parity.acquire.cta.shared::cta.b64 P, [%1], %2, 0x989680;\n\tselp.b32 %0,1,0,P;\n\t}"
            : "=r"(done) : "r"(mbar), "r"(phase) : "memory");
    }
}
__device__ __forceinline__ unsigned packh2(float a, float b) {
    __half2 h = __floats2half2_rn(a, b);
    return *reinterpret_cast<unsigned*>(&h);
}
__device__ __forceinline__ float tanh_fast(float x) {
    float r;
    asm("tanh.approx.f32 %0, %1;" : "=f"(r) : "f"(x));
    return r;
}
__device__ __forceinline__ void hmma(float* c, const unsigned* a, unsigned b0, unsigned b1) {
    asm volatile("mma.sync.aligned.m16n8k16.row.col.f32.f16.f16.f32 "
                 "{%0,%1,%2,%3}, {%4,%5,%6,%7}, {%8,%9}, {%0,%1,%2,%3};"
                 : "+f"(c[0]), "+f"(c[1]), "+f"(c[2]), "+f"(c[3])
                 : "r"(a[0]), "r"(a[1]), "r"(a[2]), "r"(a[3]), "r"(b0), "r"(b1));
}
__device__ __forceinline__ void mma8(float* acc, const unsigned* a, const uint4* bq) {
#pragma unroll
    for (int j = 0; j < 4; j++) {
        hmma(acc + (2 * j) * 4,     a, bq[j].x, bq[j].y);
        hmma(acc + (2 * j + 1) * 4, a, bq[j].z, bq[j].w);
    }
}
__device__ __forceinline__ float bsp(float s) {
    float t2 = fabsf(s - 2.0f);
    float r1 = fmaf((0.5f * t2 - 1.0f) * t2, t2, 2.0f / 3.0f);
    float am = fmaxf(2.0f - t2, 0.0f);
    float r2 = am * am * am * (1.0f / 6.0f);
    return t2 < 1.0f ? r1 : r2;
}

// ---------------- wprep: fragment-order fp16 weight images (R10 verbatim) ----------------
__global__ void prep_kernel(const float* __restrict__ fourier_weight,
                            const float* __restrict__ base_weight,
                            const float* __restrict__ spline_weight,
                            const float* __restrict__ freq_theta)
{
    int idx = blockIdx.x * blockDim.x + threadIdx.x;
    int stride = gridDim.x * blockDim.x;
    if (idx < 128) {
        float sp = log1pf(expf(freq_theta[idx]));
        g_freqw[idx] = exp10f(-(9.0f * idx) / 127.0f) * (sp + 1e-6f);
    }
    for (int w = idx; w < 126976; w += stride) {
        float w0, w1;
        if (w < 81920) {
            int f = w / 10240;
            int within = w - f * 10240;
            int ks   = within >> 10;
            int c4   = (within >> 7) & 7;
            int lane = (within >> 2) & 31;
            int q    = within & 3;
            int nt = 2 * c4 + (q >> 1);
            int n  = nt * 8 + (lane >> 2);
            int kl = (lane & 3) * 2 + (q & 1) * 8;
            int d  = 16 * f + kl;
            int s  = ks & 1, kh = ks >> 1;
            w0 = fourier_weight[((size_t)(s * 128 + n) * 128 + d)     * 5 + kh];
            w1 = fourier_weight[((size_t)(s * 128 + n) * 128 + d + 1) * 5 + kh];
        } else {
            int base = (w < 122880) ? (w & 8191) : (w - 122880);
            int ks   = base >> 10;
            int c4   = (base >> 7) & 7;
            int lane = (base >> 2) & 31;
            int q    = base & 3;
            int nt = 2 * c4 + (q >> 1);
            int n  = nt * 8 + (lane >> 2);
            int k0 = 16 * ks + (lane & 3) * 2 + (q & 1) * 8;
            if (w < 90112) {
                w0 = base_weight[n * 128 + k0];
                w1 = base_weight[n * 128 + k0 + 1];
            } else if (w < 98304) {
                int dl = k0 & 15, m = k0 >> 4;
                w0 = spline_weight[((size_t)n * 128 + dl)     * 8 + m];
                w1 = spline_weight[((size_t)n * 128 + dl + 1) * 8 + m];
            } else if (w < 122880) {
                int bb = (w - 98304) >> 13;
                int mslot = k0 >> 5, dl = k0 & 31;
                int d = 16 + bb * 32 + dl, m = mslot + 2;
                w0 = spline_weight[((size_t)n * 128 + d)     * 8 + m];
                w1 = spline_weight[((size_t)n * 128 + d + 1) * 8 + m];
            } else {
                int mslot = k0 >> 4, dl = k0 & 15;
                int d = 112 + dl, m = mslot + 2;
                w0 = spline_weight[((size_t)n * 128 + d)     * 8 + m];
                w1 = spline_weight[((size_t)n * 128 + d + 1) * 8 + m];
            }
        }
        g_B[w] = packh2(w0, w1);
    }
}

// ---------------- tprep: one (m-block, step) per CTA; R10 step bodies ----------------
__global__ void __launch_bounds__(512, 1)
tprep_kernel(const float* __restrict__ bias_fourier,
             const float* __restrict__ w1w,
             const float* __restrict__ w1b)
{
    extern __shared__ __align__(16) unsigned char smem[];
    const int tid = threadIdx.x, wid = tid >> 5, lane = tid & 31;
    const int wm = wid >> 1, wn = wid & 1;
    const int step  = blockIdx.y;
    const int knot0 = blockIdx.x * 128;

    float* s_fw  = (float*)(smem + OFF_FW);
    float* s_bf  = (float*)(smem + OFF_BF);
    float* s_w1w = (float*)(smem + OFF_W1W);
    float* s_w1b = (float*)(smem + OFF_W1B);
    float* s_xw  = (float*)(smem + OFF_XW);
    float* s_ub  = (float*)(smem + OFF_UB);
    uint32_t sb = smem_u32(smem);
    uint32_t mbar = sb + OFF_MB;

    if (tid < 128) {
        float fw = g_freqw[tid];
        float wv = w1w[tid], wb = w1b[tid];
        s_fw[tid]  = fw;
        s_bf[tid]  = bias_fourier[tid];
        s_w1w[tid] = wv;
        s_w1b[tid] = wb;
        s_xw[tid]  = 2.5f * wv;
        ((float*)(smem + OFF_XB))[tid] = fmaf(wb, 2.5f, 5.5f);
        s_ub[tid]  = fmaf(wb, 2.5f, 0.5f);
    }
    if (tid == 0)
        asm volatile("mbarrier.init.shared.b64 [%0], 1;" :: "r"(mbar) : "memory");
    __syncthreads();

    uint32_t woff  = (step < 8) ? (uint32_t)step * 10240u : 81920u + (uint32_t)(step - 8) * 8192u;
    uint32_t bytes = (step < 8) ? 40960u : ((step == 13) ? 16384u : 32768u);
    if (tid == 0) {
        asm volatile("fence.proxy.async.shared::cta;" ::: "memory");
        asm volatile("mbarrier.arrive.expect_tx.shared.b64 _, [%0], %1;"
                     :: "r"(mbar), "r"(bytes) : "memory");
        asm volatile("cp.async.bulk.shared::cluster.global.mbarrier::complete_tx::bytes [%0], [%1], %2, [%3];"
                     :: "r"(sb + OFF_B), "l"((const void*)(g_B + woff)), "r"(bytes), "r"(mbar) : "memory");
    }

    const int r0 = 16 * wm + (lane >> 2);
    const int c2 = (lane & 3) * 2;
    const int boff0 = (wn * 128 + lane) * 16;
    const float t0 = ((float)(knot0 + r0)     - 1.0f) * (1.0f / HINV);
    const float t1 = ((float)(knot0 + r0 + 8) - 1.0f) * (1.0f / HINV);

#define LOADB(bq, bp, ksv)                                                                   \
    {                                                                                        \
        (bq)[0] = *(const uint4*)((bp) + (ksv) * 4096 + boff0);                              \
        (bq)[1] = *(const uint4*)((bp) + (ksv) * 4096 + boff0 + 512);                        \
        (bq)[2] = *(const uint4*)((bp) + (ksv) * 4096 + boff0 + 1024);                       \
        (bq)[3] = *(const uint4*)((bp) + (ksv) * 4096 + boff0 + 1536);                       \
    }

    float acc[32];
#pragma unroll
    for (int i = 0; i < 32; i++) acc[i] = 0.0f;

    mbar_wait(mbar, 0u);
    const unsigned char* bp = smem + OFF_B;

    if (step < 8) {
        // fourier chunk p=step : Chebyshev recurrence (R10 verbatim)
        const int p = step;
        float t2[8], ck[8], sk[8], cp[8], sp_[8];
        uint4 bb[2][4];
        LOADB(bb[0], bp, 0);
#pragma unroll
        for (int ai = 0; ai < 4; ai++) {
            int d = 16 * p + c2 + (ai & 1) + (ai >> 1) * 8;
            float fw = s_fw[d], bf = s_bf[d];
            __sincosf(fmaf(t0, fw, bf), &sk[2 * ai],     &ck[2 * ai]);
            __sincosf(fmaf(t1, fw, bf), &sk[2 * ai + 1], &ck[2 * ai + 1]);
            t2[2 * ai]     = ck[2 * ai]     + ck[2 * ai];
            t2[2 * ai + 1] = ck[2 * ai + 1] + ck[2 * ai + 1];
            cp[2 * ai] = 1.0f; cp[2 * ai + 1] = 1.0f;
            sp_[2 * ai] = 0.0f; sp_[2 * ai + 1] = 0.0f;
        }
#pragma unroll
        for (int ks = 0; ks < 10; ks++) {
            if (ks + 1 < 10) LOADB(bb[(ks + 1) & 1], bp, ks + 1);
            if (ks >= 2 && (ks & 1) == 0) {
#pragma unroll
                for (int i = 0; i < 8; i++) {
                    float cn = fmaf(t2[i], ck[i], -cp[i]);
                    float sn = fmaf(t2[i], sk[i], -sp_[i]);
                    cp[i] = ck[i]; sp_[i] = sk[i];
                    ck[i] = cn; sk[i] = sn;
                }
            }
            unsigned a[4];
            if (ks & 1) {
                a[0] = packh2(sk[0], sk[2]); a[1] = packh2(sk[1], sk[3]);
                a[2] = packh2(sk[4], sk[6]); a[3] = packh2(sk[5], sk[7]);
            } else {
                a[0] = packh2(ck[0], ck[2]); a[1] = packh2(ck[1], ck[3]);
                a[2] = packh2(ck[4], ck[6]); a[3] = packh2(ck[5], ck[7]);
            }
            mma8(acc, a, bb[ks & 1]);
        }
    } else if (step == 8) {
        // tanh
        uint4 bb[2][4];
        LOADB(bb[0], bp, 0);
#pragma unroll
        for (int ks = 0; ks < 8; ks++) {
            if (ks + 1 < 8) LOADB(bb[(ks + 1) & 1], bp, ks + 1);
            unsigned at[4];
#pragma unroll
            for (int kb = 0; kb < 2; kb++) {
                int d = 16 * ks + 8 * kb + c2;
                float2 wv2 = *(const float2*)&s_w1w[d];
                float2 wb2 = *(const float2*)&s_w1b[d];
                float v00 = tanh_fast(fmaf(t0, wv2.x, wb2.x));
                float v01 = tanh_fast(fmaf(t1, wv2.x, wb2.x));
                float v10 = tanh_fast(fmaf(t0, wv2.y, wb2.y));
                float v11 = tanh_fast(fmaf(t1, wv2.y, wb2.y));
                at[2 * kb]     = packh2(v00, v10);
                at[2 * kb + 1] = packh2(v01, v11);
            }
            mma8(acc, at, bb[ks & 1]);
        }
    } else if (step == 9) {
        // spline g0 full m-major
        uint4 bb[2][4];
        LOADB(bb[0], bp, 0);
        float xiA[4], xiB[4];
#pragma unroll
        for (int kb = 0; kb < 2; kb++) {
            int d = 8 * kb + c2;
            float2 xw2 = *(const float2*)&s_xw[d];
            float2 xb2 = *(const float2*)((float*)(smem + OFF_XB) + d);
            xiA[2 * kb]     = fmaf(t0, xw2.x, xb2.x);
            xiA[2 * kb + 1] = fmaf(t0, xw2.y, xb2.y);
            xiB[2 * kb]     = fmaf(t1, xw2.x, xb2.x);
            xiB[2 * kb + 1] = fmaf(t1, xw2.y, xb2.y);
        }
#pragma unroll
        for (int ks = 0; ks < 8; ks++) {
            if (ks + 1 < 8) LOADB(bb[(ks + 1) & 1], bp, ks + 1);
            const float fks = (float)ks;
            unsigned a0[4];
#pragma unroll
            for (int kb = 0; kb < 2; kb++) {
                a0[2 * kb]     = packh2(bsp(xiA[2 * kb] - fks), bsp(xiA[2 * kb + 1] - fks));
                a0[2 * kb + 1] = packh2(bsp(xiB[2 * kb] - fks), bsp(xiB[2 * kb + 1] - fks));
            }
            mma8(acc, a0, bb[ks & 1]);
        }
    } else {
#define SP_BASES(ai, dval, uB0, uB1, uB2, uB3)                                               \
    {                                                                                        \
        float xw = s_xw[dval], ub = s_ub[dval];                                              \
        float u0 = fmaf(t0, xw, ub);                                                         \
        float u1 = fmaf(t1, xw, ub);                                                         \
        float um = 1.0f - u0, u2 = u0 * u0;                                                  \
        uB0[2*(ai)] = um * um * (um * (1.0f/6.0f));                                          \
        uB3[2*(ai)] = u2 * (u0 * (1.0f/6.0f));                                               \
        uB1[2*(ai)] = fmaf(u2, fmaf(u0, 0.5f, -1.0f), 2.0f/3.0f);                            \
        uB2[2*(ai)] = 1.0f - uB0[2*(ai)] - uB1[2*(ai)] - uB3[2*(ai)];                        \
        um = 1.0f - u1; u2 = u1 * u1;                                                        \
        uB0[2*(ai)+1] = um * um * (um * (1.0f/6.0f));                                        \
        uB3[2*(ai)+1] = u2 * (u1 * (1.0f/6.0f));                                             \
        uB1[2*(ai)+1] = fmaf(u2, fmaf(u1, 0.5f, -1.0f), 2.0f/3.0f);                          \
        uB2[2*(ai)+1] = 1.0f - uB0[2*(ai)+1] - uB1[2*(ai)+1] - uB3[2*(ai)+1];                \
    }
#define SP_MMA2(Barr, bqv)                                                                   \
    {                                                                                        \
        unsigned a[4];                                                                       \
        a[0] = packh2(Barr[0], Barr[2]); a[1] = packh2(Barr[1], Barr[3]);                    \
        a[2] = packh2(Barr[4], Barr[6]); a[3] = packh2(Barr[5], Barr[7]);                    \
        mma8(acc, a, bqv);                                                                   \
    }
        if (step <= 12) {
            const int bbk = step - 10;
#pragma unroll
            for (int par = 0; par < 2; par++) {
                float B0[8], B1[8], B2[8], B3[8];
                uint4 q0[4], q1[4];
                LOADB(q0, bp, par);
#pragma unroll
                for (int ai = 0; ai < 4; ai++) {
                    int d = 16 + bbk * 32 + par * 16 + c2 + (ai & 1) + (ai >> 1) * 8;
                    SP_BASES(ai, d, B0, B1, B2, B3)
                }
                LOADB(q1, bp, 2 + par);
                SP_MMA2(B0, q0)
                LOADB(q0, bp, 4 + par);
                SP_MMA2(B1, q1)
                LOADB(q1, bp, 6 + par);
                SP_MMA2(B2, q0)
                SP_MMA2(B3, q1)
            }
        } else {
            float B0[8], B1[8], B2[8], B3[8];
            uint4 q0[4], q1[4];
            LOADB(q0, bp, 0);
#pragma unroll
            for (int ai = 0; ai < 4; ai++) {
                int d = 112 + c2 + (ai & 1) + (ai >> 1) * 8;
                SP_BASES(ai, d, B0, B1, B2, B3)
            }
            LOADB(q1, bp, 1);
            SP_MMA2(B0, q0)
            LOADB(q0, bp, 2);
            SP_MMA2(B1, q1)
            LOADB(q1, bp, 3);
            SP_MMA2(B2, q0)
            SP_MMA2(B3, q1)
        }
    }

    // store partial tile: g_part[step][knot][c], c in [0,128)
    float* d0 = g_part + ((size_t)step * GKNOTS + knot0 + r0) * 128;
    float* d1 = d0 + 8 * 128;
#pragma unroll
    for (int t = 0; t < 8; t++) {
        int col = wn * 64 + t * 8 + c2;
        *(float2*)&d0[col] = make_float2(acc[4 * t],     acc[4 * t + 1]);
        *(float2*)&d1[col] = make_float2(acc[4 * t + 2], acc[4 * t + 3]);
    }
}

// ---------------- pack: sum partials -> fp16 table (x0.5 concat scale) ----------------
__global__ void pack_kernel()
{
    int idx = blockIdx.x * blockDim.x + threadIdx.x;   // 65536
    int row = idx >> 7, c = idx & 127;
    float sF = 0.0f, sS = 0.0f;
#pragma unroll
    for (int s = 0; s < 8; s++)  sF += g_part[((size_t)s * GKNOTS + row) * 128 + c];
#pragma unroll
    for (int s = 8; s < 14; s++) sS += g_part[((size_t)s * GKNOTS + row) * 128 + c];
    g_T16[row * 256 + c]       = __float2half_rn(0.5f * sF);
    g_T16[row * 256 + 128 + c] = __float2half_rn(0.5f * sS);
}

// ---------------- main: cubic-Lagrange interpolation + LN ----------------
__global__ void __launch_bounds__(512, 1)
interp_kernel(const float* __restrict__ ts,
              const float* __restrict__ ln_w,
              const float* __restrict__ ln_b,
              const float* __restrict__ scale_w,
              float* __restrict__ out)
{
    const int tid = threadIdx.x;
    const int rloc = tid >> 2, q = tid & 3;
    const int row = blockIdx.x * 128 + rloc;

    float t = ts[row];
    float u = fmaf(t, HINV, 1.0f);
    int j = (int)floorf(u);
    j = max(1, min(509, j));
    float f = u - (float)j;
    float fm1 = f - 1.0f, fm2 = f - 2.0f, fp1 = f + 1.0f;
    float lw[4];
    lw[0] = -f * fm1 * fm2 * (1.0f / 6.0f);
    lw[1] = fp1 * fm1 * fm2 * 0.5f;
    lw[2] = -fp1 * f * fm2 * 0.5f;
    lw[3] = fp1 * f * fm1 * (1.0f / 6.0f);

    float acc[64];
#pragma unroll
    for (int i = 0; i < 64; i++) acc[i] = 0.0f;
#pragma unroll
    for (int k = 0; k < 4; k++) {
        const uint4* p = (const uint4*)(g_T16 + (size_t)(j - 1 + k) * 256 + q * 64);
        float wk = lw[k];
#pragma unroll
        for (int b = 0; b < 8; b++) {
            uint4 v = __ldg(p + b);
            __half2 h;
            float2 x;
            h = *(__half2*)&v.x; x = __half22float2(h);
            acc[b * 8 + 0] = fmaf(wk, x.x, acc[b * 8 + 0]);
            acc[b * 8 + 1] = fmaf(wk, x.y, acc[b * 8 + 1]);
            h = *(__half2*)&v.y; x = __half22float2(h);
            acc[b * 8 + 2] = fmaf(wk, x.x, acc[b * 8 + 2]);
            acc[b * 8 + 3] = fmaf(wk, x.y, acc[b * 8 + 3]);
            h = *(__half2*)&v.z; x = __half22float2(h);
            acc[b * 8 + 4] = fmaf(wk, x.x, acc[b * 8 + 4]);
            acc[b * 8 + 5] = fmaf(wk, x.y, acc[b * 8 + 5]);
            h = *(__half2*)&v.w; x = __half22float2(h);
            acc[b * 8 + 6] = fmaf(wk, x.x, acc[b * 8 + 6]);
            acc[b * 8 + 7] = fmaf(wk, x.y, acc[b * 8 + 7]);
        }
    }

    float sum = 0.0f, sq = 0.0f;
#pragma unroll
    for (int i = 0; i < 64; i++) { sum += acc[i]; sq += acc[i] * acc[i]; }
#pragma unroll
    for (int off = 1; off <= 2; off <<= 1) {
        sum += __shfl_xor_sync(0xffffffffu, sum, off);
        sq  += __shfl_xor_sync(0xffffffffu, sq,  off);
    }
    float mu   = sum * (1.0f / 256.0f);
    float rstd = rsqrtf(sq * (1.0f / 256.0f) - mu * mu + 1e-5f);

    float* op = out + (size_t)row * 256 + q * 64;
#pragma unroll
    for (int b = 0; b < 16; b++) {
        float4 w4 = __ldg((const float4*)&ln_w[q * 64 + b * 4]);
        float4 b4 = __ldg((const float4*)&ln_b[q * 64 + b * 4]);
        float4 s4 = __ldg((const float4*)&scale_w[q * 64 + b * 4]);
        float4 o;
        o.x = ((acc[b * 4 + 0] - mu) * rstd * w4.x + b4.x) * s4.x;
        o.y = ((acc[b * 4 + 1] - mu) * rstd * w4.y + b4.y) * s4.y;
        o.z = ((acc[b * 4 + 2] - mu) * rstd * w4.z + b4.z) * s4.z;
        o.w = ((acc[b * 4 + 3] - mu) * rstd * w4.w + b4.w) * s4.w;
        *(float4*)&op[b * 4] = o;
    }
}

extern "C" void kernel_launch(void* const* d_in, const int* in_sizes, int n_in,
                              void* d_out, int out_size)
{
    const float* timestamps   = (const float*)d_in[0];
    const float* freq_theta   = (const float*)d_in[1];
    const float* bias_fourier = (const float*)d_in[2];
    const float* fourier_w    = (const float*)d_in[3];
    const float* w1w          = (const float*)d_in[4];
    const float* w1b          = (const float*)d_in[5];
    const float* base_w       = (const float*)d_in[6];
    const float* spline_w     = (const float*)d_in[7];
    const float* scale_w      = (const float*)d_in[8];
    const float* ln_w         = (const float*)d_in[9];
    const float* ln_b         = (const float*)d_in[10];
    float* out = (float*)d_out;

    int nrows = in_sizes[0];   // 16384
    cudaFuncSetAttribute(tprep_kernel, cudaFuncAttributeMaxDynamicSharedMemorySize, TP_SMEM);

    prep_kernel<<<152, 256>>>(fourier_w, base_w, spline_w, freq_theta);
    tprep_kernel<<<dim3(GKNOTS / 128, 14), 512, TP_SMEM>>>(bias_fourier, w1w, w1b);
    pack_kernel<<<64, 1024>>>();
    interp_kernel<<<nrows / 128, 512>>>(timestamps, ln_w, ln_b, scale_w, out);
}

// round 16
// speedup vs baseline: 2.0564x; 1.5939x over previous
#include <cuda_runtime.h>
#include <cuda_fp16.h>
#include <cstdint>

// ---------------- table config ----------------
// G=256 knots, tau_j=(j-1)/253, j=0..255; t in [0,1) -> u=t*253+1, j=floor(u) in [1,253]
#define GKNOTS 256
#define HINV   253.0f

// tprep smem: single 40KB B slot + params
#define OFF_B    0
#define OFF_FW   40960
#define OFF_BF   (OFF_FW + 512)
#define OFF_W1W  (OFF_BF + 512)
#define OFF_W1B  (OFF_W1W + 512)
#define OFF_XW   (OFF_W1B + 512)
#define OFF_XB   (OFF_XW + 512)
#define OFF_UB   (OFF_XB + 512)
#define OFF_MB   (OFF_UB + 512)
#define TP_SMEM  (OFF_MB + 32)

// g_B: fp16 B-fragment images, 14 steps (layout identical to R9/R10)
__device__ __align__(16) unsigned g_B[126976];
__device__ float g_freqw[128];
__device__ float g_part[14 * GKNOTS * 128];          // per-step partial tiles
__device__ __align__(16) __half g_T16[GKNOTS * 256]; // final table (128KB)

__device__ __forceinline__ uint32_t smem_u32(const void* p) {
    uint32_t a;
    asm("{ .reg .u64 t; cvta.to.shared.u64 t, %1; cvt.u32.u64 %0, t; }" : "=r"(a) : "l"(p));
    return a;
}
__device__ __forceinline__ void mbar_wait(uint32_t mbar, uint32_t phase) {
    uint32_t done = 0;
    while (!done) {
        asm volatile(
            "{\n\t.reg .pred P;\n\tmbarrier.try_wait.parity.acquire.cta.shared::cta.b64 P, [%1], %2, 0x989680;\n\tselp.b32 %0,1,0,P;\n\t}"
            : "=r"(done) : "r"(mbar), "r"(phase) : "memory");
    }
}
__device__ __forceinline__ unsigned packh2(float a, float b) {
    __half2 h = __floats2half2_rn(a, b);
    return *reinterpret_cast<unsigned*>(&h);
}
__device__ __forceinline__ float tanh_fast(float x) {
    float r;
    asm("tanh.approx.f32 %0, %1;" : "=f"(r) : "f"(x));
    return r;
}
__device__ __forceinline__ void hmma(float* c, const unsigned* a, unsigned b0, unsigned b1) {
    asm volatile("mma.sync.aligned.m16n8k16.row.col.f32.f16.f16.f32 "
                 "{%0,%1,%2,%3}, {%4,%5,%6,%7}, {%8,%9}, {%0,%1,%2,%3};"
                 : "+f"(c[0]), "+f"(c[1]), "+f"(c[2]), "+f"(c[3])
                 : "r"(a[0]), "r"(a[1]), "r"(a[2]), "r"(a[3]), "r"(b0), "r"(b1));
}
__device__ __forceinline__ void mma8(float* acc, const unsigned* a, const uint4* bq) {
#pragma unroll
    for (int j = 0; j < 4; j++) {
        hmma(acc + (2 * j) * 4,     a, bq[j].x, bq[j].y);
        hmma(acc + (2 * j + 1) * 4, a, bq[j].z, bq[j].w);
    }
}
__device__ __forceinline__ float bsp(float s) {
    float t2 = fabsf(s - 2.0f);
    float r1 = fmaf((0.5f * t2 - 1.0f) * t2, t2, 2.0f / 3.0f);
    float am = fmaxf(2.0f - t2, 0.0f);
    float r2 = am * am * am * (1.0f / 6.0f);
    return t2 < 1.0f ? r1 : r2;
}

// ---------------- wprep: fragment-order fp16 weight images (R10 verbatim) ----------------
__global__ void prep_kernel(const float* __restrict__ fourier_weight,
                            const float* __restrict__ base_weight,
                            const float* __restrict__ spline_weight,
                            const float* __restrict__ freq_theta)
{
    int idx = blockIdx.x * blockDim.x + threadIdx.x;
    int stride = gridDim.x * blockDim.x;
    if (idx < 128) {
        float sp = log1pf(expf(freq_theta[idx]));
        g_freqw[idx] = exp10f(-(9.0f * idx) / 127.0f) * (sp + 1e-6f);
    }
    for (int w = idx; w < 126976; w += stride) {
        float w0, w1;
        if (w < 81920) {
            int f = w / 10240;
            int within = w - f * 10240;
            int ks   = within >> 10;
            int c4   = (within >> 7) & 7;
            int lane = (within >> 2) & 31;
            int q    = within & 3;
            int nt = 2 * c4 + (q >> 1);
            int n  = nt * 8 + (lane >> 2);
            int kl = (lane & 3) * 2 + (q & 1) * 8;
            int d  = 16 * f + kl;
            int s  = ks & 1, kh = ks >> 1;
            w0 = fourier_weight[((size_t)(s * 128 + n) * 128 + d)     * 5 + kh];
            w1 = fourier_weight[((size_t)(s * 128 + n) * 128 + d + 1) * 5 + kh];
        } else {
            int base = (w < 122880) ? (w & 8191) : (w - 122880);
            int ks   = base >> 10;
            int c4   = (base >> 7) & 7;
            int lane = (base >> 2) & 31;
            int q    = base & 3;
            int nt = 2 * c4 + (q >> 1);
            int n  = nt * 8 + (lane >> 2);
            int k0 = 16 * ks + (lane & 3) * 2 + (q & 1) * 8;
            if (w < 90112) {
                w0 = base_weight[n * 128 + k0];
                w1 = base_weight[n * 128 + k0 + 1];
            } else if (w < 98304) {
                int dl = k0 & 15, m = k0 >> 4;
                w0 = spline_weight[((size_t)n * 128 + dl)     * 8 + m];
                w1 = spline_weight[((size_t)n * 128 + dl + 1) * 8 + m];
            } else if (w < 122880) {
                int bb = (w - 98304) >> 13;
                int mslot = k0 >> 5, dl = k0 & 31;
                int d = 16 + bb * 32 + dl, m = mslot + 2;
                w0 = spline_weight[((size_t)n * 128 + d)     * 8 + m];
                w1 = spline_weight[((size_t)n * 128 + d + 1) * 8 + m];
            } else {
                int mslot = k0 >> 4, dl = k0 & 15;
                int d = 112 + dl, m = mslot + 2;
                w0 = spline_weight[((size_t)n * 128 + d)     * 8 + m];
                w1 = spline_weight[((size_t)n * 128 + d + 1) * 8 + m];
            }
        }
        g_B[w] = packh2(w0, w1);
    }
}

// ---------------- tprep: one (m-block, step) per CTA; R10 step bodies ----------------
__global__ void __launch_bounds__(512, 1)
tprep_kernel(const float* __restrict__ bias_fourier,
             const float* __restrict__ w1w,
             const float* __restrict__ w1b)
{
    extern __shared__ __align__(16) unsigned char smem[];
    const int tid = threadIdx.x, wid = tid >> 5, lane = tid & 31;
    const int wm = wid >> 1, wn = wid & 1;
    const int step  = blockIdx.y;
    const int knot0 = blockIdx.x * 128;

    float* s_fw  = (float*)(smem + OFF_FW);
    float* s_bf  = (float*)(smem + OFF_BF);
    float* s_w1w = (float*)(smem + OFF_W1W);
    float* s_w1b = (float*)(smem + OFF_W1B);
    float* s_xw  = (float*)(smem + OFF_XW);
    float* s_ub  = (float*)(smem + OFF_UB);
    uint32_t sb = smem_u32(smem);
    uint32_t mbar = sb + OFF_MB;

    if (tid < 128) {
        float fw = g_freqw[tid];
        float wv = w1w[tid], wb = w1b[tid];
        s_fw[tid]  = fw;
        s_bf[tid]  = bias_fourier[tid];
        s_w1w[tid] = wv;
        s_w1b[tid] = wb;
        s_xw[tid]  = 2.5f * wv;
        ((float*)(smem + OFF_XB))[tid] = fmaf(wb, 2.5f, 5.5f);
        s_ub[tid]  = fmaf(wb, 2.5f, 0.5f);
    }
    if (tid == 0)
        asm volatile("mbarrier.init.shared.b64 [%0], 1;" :: "r"(mbar) : "memory");
    __syncthreads();

    uint32_t woff  = (step < 8) ? (uint32_t)step * 10240u : 81920u + (uint32_t)(step - 8) * 8192u;
    uint32_t bytes = (step < 8) ? 40960u : ((step == 13) ? 16384u : 32768u);
    if (tid == 0) {
        asm volatile("fence.proxy.async.shared::cta;" ::: "memory");
        asm volatile("mbarrier.arrive.expect_tx.shared.b64 _, [%0], %1;"
                     :: "r"(mbar), "r"(bytes) : "memory");
        asm volatile("cp.async.bulk.shared::cluster.global.mbarrier::complete_tx::bytes [%0], [%1], %2, [%3];"
                     :: "r"(sb + OFF_B), "l"((const void*)(g_B + woff)), "r"(bytes), "r"(mbar) : "memory");
    }

    const int r0 = 16 * wm + (lane >> 2);
    const int c2 = (lane & 3) * 2;
    const int boff0 = (wn * 128 + lane) * 16;
    const float t0 = ((float)(knot0 + r0)     - 1.0f) * (1.0f / HINV);
    const float t1 = ((float)(knot0 + r0 + 8) - 1.0f) * (1.0f / HINV);

#define LOADB(bq, bp, ksv)                                                                   \
    {                                                                                        \
        (bq)[0] = *(const uint4*)((bp) + (ksv) * 4096 + boff0);                              \
        (bq)[1] = *(const uint4*)((bp) + (ksv) * 4096 + boff0 + 512);                        \
        (bq)[2] = *(const uint4*)((bp) + (ksv) * 4096 + boff0 + 1024);                       \
        (bq)[3] = *(const uint4*)((bp) + (ksv) * 4096 + boff0 + 1536);                       \
    }

    float acc[32];
#pragma unroll
    for (int i = 0; i < 32; i++) acc[i] = 0.0f;

    mbar_wait(mbar, 0u);
    const unsigned char* bp = smem + OFF_B;

    if (step < 8) {
        const int p = step;
        float t2[8], ck[8], sk[8], cp[8], sp_[8];
        uint4 bb[2][4];
        LOADB(bb[0], bp, 0);
#pragma unroll
        for (int ai = 0; ai < 4; ai++) {
            int d = 16 * p + c2 + (ai & 1) + (ai >> 1) * 8;
            float fw = s_fw[d], bf = s_bf[d];
            __sincosf(fmaf(t0, fw, bf), &sk[2 * ai],     &ck[2 * ai]);
            __sincosf(fmaf(t1, fw, bf), &sk[2 * ai + 1], &ck[2 * ai + 1]);
            t2[2 * ai]     = ck[2 * ai]     + ck[2 * ai];
            t2[2 * ai + 1] = ck[2 * ai + 1] + ck[2 * ai + 1];
            cp[2 * ai] = 1.0f; cp[2 * ai + 1] = 1.0f;
            sp_[2 * ai] = 0.0f; sp_[2 * ai + 1] = 0.0f;
        }
#pragma unroll
        for (int ks = 0; ks < 10; ks++) {
            if (ks + 1 < 10) LOADB(bb[(ks + 1) & 1], bp, ks + 1);
            if (ks >= 2 && (ks & 1) == 0) {
#pragma unroll
                for (int i = 0; i < 8; i++) {
                    float cn = fmaf(t2[i], ck[i], -cp[i]);
                    float sn = fmaf(t2[i], sk[i], -sp_[i]);
                    cp[i] = ck[i]; sp_[i] = sk[i];
                    ck[i] = cn; sk[i] = sn;
                }
            }
            unsigned a[4];
            if (ks & 1) {
                a[0] = packh2(sk[0], sk[2]); a[1] = packh2(sk[1], sk[3]);
                a[2] = packh2(sk[4], sk[6]); a[3] = packh2(sk[5], sk[7]);
            } else {
                a[0] = packh2(ck[0], ck[2]); a[1] = packh2(ck[1], ck[3]);
                a[2] = packh2(ck[4], ck[6]); a[3] = packh2(ck[5], ck[7]);
            }
            mma8(acc, a, bb[ks & 1]);
        }
    } else if (step == 8) {
        uint4 bb[2][4];
        LOADB(bb[0], bp, 0);
#pragma unroll
        for (int ks = 0; ks < 8; ks++) {
            if (ks + 1 < 8) LOADB(bb[(ks + 1) & 1], bp, ks + 1);
            unsigned at[4];
#pragma unroll
            for (int kb = 0; kb < 2; kb++) {
                int d = 16 * ks + 8 * kb + c2;
                float2 wv2 = *(const float2*)&s_w1w[d];
                float2 wb2 = *(const float2*)&s_w1b[d];
                float v00 = tanh_fast(fmaf(t0, wv2.x, wb2.x));
                float v01 = tanh_fast(fmaf(t1, wv2.x, wb2.x));
                float v10 = tanh_fast(fmaf(t0, wv2.y, wb2.y));
                float v11 = tanh_fast(fmaf(t1, wv2.y, wb2.y));
                at[2 * kb]     = packh2(v00, v10);
                at[2 * kb + 1] = packh2(v01, v11);
            }
            mma8(acc, at, bb[ks & 1]);
        }
    } else if (step == 9) {
        uint4 bb[2][4];
        LOADB(bb[0], bp, 0);
        float xiA[4], xiB[4];
#pragma unroll
        for (int kb = 0; kb < 2; kb++) {
            int d = 8 * kb + c2;
            float2 xw2 = *(const float2*)&s_xw[d];
            float2 xb2 = *(const float2*)((float*)(smem + OFF_XB) + d);
            xiA[2 * kb]     = fmaf(t0, xw2.x, xb2.x);
            xiA[2 * kb + 1] = fmaf(t0, xw2.y, xb2.y);
            xiB[2 * kb]     = fmaf(t1, xw2.x, xb2.x);
            xiB[2 * kb + 1] = fmaf(t1, xw2.y, xb2.y);
        }
#pragma unroll
        for (int ks = 0; ks < 8; ks++) {
            if (ks + 1 < 8) LOADB(bb[(ks + 1) & 1], bp, ks + 1);
            const float fks = (float)ks;
            unsigned a0[4];
#pragma unroll
            for (int kb = 0; kb < 2; kb++) {
                a0[2 * kb]     = packh2(bsp(xiA[2 * kb] - fks), bsp(xiA[2 * kb + 1] - fks));
                a0[2 * kb + 1] = packh2(bsp(xiB[2 * kb] - fks), bsp(xiB[2 * kb + 1] - fks));
            }
            mma8(acc, a0, bb[ks & 1]);
        }
    } else {
#define SP_BASES(ai, dval, uB0, uB1, uB2, uB3)                                               \
    {                                                                                        \
        float xw = s_xw[dval], ub = s_ub[dval];                                              \
        float u0 = fmaf(t0, xw, ub);                                                         \
        float u1 = fmaf(t1, xw, ub);                                                         \
        float um = 1.0f - u0, u2 = u0 * u0;                                                  \
        uB0[2*(ai)] = um * um * (um * (1.0f/6.0f));                                          \
        uB3[2*(ai)] = u2 * (u0 * (1.0f/6.0f));                                               \
        uB1[2*(ai)] = fmaf(u2, fmaf(u0, 0.5f, -1.0f), 2.0f/3.0f);                            \
        uB2[2*(ai)] = 1.0f - uB0[2*(ai)] - uB1[2*(ai)] - uB3[2*(ai)];                        \
        um = 1.0f - u1; u2 = u1 * u1;                                                        \
        uB0[2*(ai)+1] = um * um * (um * (1.0f/6.0f));                                        \
        uB3[2*(ai)+1] = u2 * (u1 * (1.0f/6.0f));                                             \
        uB1[2*(ai)+1] = fmaf(u2, fmaf(u1, 0.5f, -1.0f), 2.0f/3.0f);                          \
        uB2[2*(ai)+1] = 1.0f - uB0[2*(ai)+1] - uB1[2*(ai)+1] - uB3[2*(ai)+1];                \
    }
#define SP_MMA2(Barr, bqv)                                                                   \
    {                                                                                        \
        unsigned a[4];                                                                       \
        a[0] = packh2(Barr[0], Barr[2]); a[1] = packh2(Barr[1], Barr[3]);                    \
        a[2] = packh2(Barr[4], Barr[6]); a[3] = packh2(Barr[5], Barr[7]);                    \
        mma8(acc, a, bqv);                                                                   \
    }
        if (step <= 12) {
            const int bbk = step - 10;
#pragma unroll
            for (int par = 0; par < 2; par++) {
                float B0[8], B1[8], B2[8], B3[8];
                uint4 q0[4], q1[4];
                LOADB(q0, bp, par);
#pragma unroll
                for (int ai = 0; ai < 4; ai++) {
                    int d = 16 + bbk * 32 + par * 16 + c2 + (ai & 1) + (ai >> 1) * 8;
                    SP_BASES(ai, d, B0, B1, B2, B3)
                }
                LOADB(q1, bp, 2 + par);
                SP_MMA2(B0, q0)
                LOADB(q0, bp, 4 + par);
                SP_MMA2(B1, q1)
                LOADB(q1, bp, 6 + par);
                SP_MMA2(B2, q0)
                SP_MMA2(B3, q1)
            }
        } else {
            float B0[8], B1[8], B2[8], B3[8];
            uint4 q0[4], q1[4];
            LOADB(q0, bp, 0);
#pragma unroll
            for (int ai = 0; ai < 4; ai++) {
                int d = 112 + c2 + (ai & 1) + (ai >> 1) * 8;
                SP_BASES(ai, d, B0, B1, B2, B3)
            }
            LOADB(q1, bp, 1);
            SP_MMA2(B0, q0)
            LOADB(q0, bp, 2);
            SP_MMA2(B1, q1)
            LOADB(q1, bp, 3);
            SP_MMA2(B2, q0)
            SP_MMA2(B3, q1)
        }
    }

    float* d0 = g_part + ((size_t)step * GKNOTS + knot0 + r0) * 128;
    float* d1 = d0 + 8 * 128;
#pragma unroll
    for (int t = 0; t < 8; t++) {
        int col = wn * 64 + t * 8 + c2;
        *(float2*)&d0[col] = make_float2(acc[4 * t],     acc[4 * t + 1]);
        *(float2*)&d1[col] = make_float2(acc[4 * t + 2], acc[4 * t + 3]);
    }
}

// ---------------- pack: sum partials -> fp16 table (x0.5 concat scale) ----------------
__global__ void pack_kernel()
{
    int idx = blockIdx.x * blockDim.x + threadIdx.x;   // 32768
    int row = idx >> 7, c = idx & 127;
    float sF = 0.0f, sS = 0.0f;
#pragma unroll
    for (int s = 0; s < 8; s++)  sF += g_part[((size_t)s * GKNOTS + row) * 128 + c];
#pragma unroll
    for (int s = 8; s < 14; s++) sS += g_part[((size_t)s * GKNOTS + row) * 128 + c];
    g_T16[row * 256 + c]       = __float2half_rn(0.5f * sF);
    g_T16[row * 256 + 128 + c] = __float2half_rn(0.5f * sS);
}

// ---------------- main: warp-per-row cubic-Lagrange interpolation + LN ----------------
__global__ void __launch_bounds__(512, 1)
interp_kernel(const float* __restrict__ ts,
              const float* __restrict__ ln_w,
              const float* __restrict__ ln_b,
              const float* __restrict__ scale_w,
              float* __restrict__ out)
{
    const int wid = threadIdx.x >> 5, lane = threadIdx.x & 31;
    const int rowbase = blockIdx.x * 32 + wid * 2;

    // per-lane LN params for cols lane*8 .. lane*8+7 (reused across both rows)
    const int col = lane * 8;
    float4 w4a = __ldg((const float4*)&ln_w[col]);
    float4 w4b = __ldg((const float4*)&ln_w[col + 4]);
    float4 b4a = __ldg((const float4*)&ln_b[col]);
    float4 b4b = __ldg((const float4*)&ln_b[col + 4]);
    float4 s4a = __ldg((const float4*)&scale_w[col]);
    float4 s4b = __ldg((const float4*)&scale_w[col + 4]);

#pragma unroll
    for (int rr = 0; rr < 2; rr++) {
        int row = rowbase + rr;
        float t = __ldg(&ts[row]);
        float u = fmaf(t, HINV, 1.0f);
        int j = (int)floorf(u);
        j = max(1, min(253, j));
        float f = u - (float)j;
        float fm1 = f - 1.0f, fm2 = f - 2.0f, fp1 = f + 1.0f;
        float lw0 = -f * fm1 * fm2 * (1.0f / 6.0f);
        float lw1 = fp1 * fm1 * fm2 * 0.5f;
        float lw2 = -fp1 * f * fm2 * 0.5f;
        float lw3 = fp1 * f * fm1 * (1.0f / 6.0f);

        // coalesced: lane*16B within the 512B table row; 4 consecutive rows
        const uint4* p = (const uint4*)g_T16 + (size_t)(j - 1) * 32 + lane;
        uint4 v0 = __ldg(p);
        uint4 v1 = __ldg(p + 32);
        uint4 v2 = __ldg(p + 64);
        uint4 v3 = __ldg(p + 96);

        float acc[8];
#pragma unroll
        for (int h = 0; h < 4; h++) {
            unsigned u0 = (&v0.x)[h], u1 = (&v1.x)[h], u2 = (&v2.x)[h], u3 = (&v3.x)[h];
            float2 x0 = __half22float2(*(__half2*)&u0);
            float2 x1 = __half22float2(*(__half2*)&u1);
            float2 x2 = __half22float2(*(__half2*)&u2);
            float2 x3 = __half22float2(*(__half2*)&u3);
            acc[2 * h]     = fmaf(lw3, x3.x, fmaf(lw2, x2.x, fmaf(lw1, x1.x, lw0 * x0.x)));
            acc[2 * h + 1] = fmaf(lw3, x3.y, fmaf(lw2, x2.y, fmaf(lw1, x1.y, lw0 * x0.y)));
        }

        float sum = 0.0f, sq = 0.0f;
#pragma unroll
        for (int i = 0; i < 8; i++) { sum += acc[i]; sq += acc[i] * acc[i]; }
#pragma unroll
        for (int off = 16; off > 0; off >>= 1) {
            sum += __shfl_xor_sync(0xffffffffu, sum, off);
            sq  += __shfl_xor_sync(0xffffffffu, sq,  off);
        }
        float mu   = sum * (1.0f / 256.0f);
        float rstd = rsqrtf(sq * (1.0f / 256.0f) - mu * mu + 1e-5f);

        float4 oa, ob;
        oa.x = ((acc[0] - mu) * rstd * w4a.x + b4a.x) * s4a.x;
        oa.y = ((acc[1] - mu) * rstd * w4a.y + b4a.y) * s4a.y;
        oa.z = ((acc[2] - mu) * rstd * w4a.z + b4a.z) * s4a.z;
        oa.w = ((acc[3] - mu) * rstd * w4a.w + b4a.w) * s4a.w;
        ob.x = ((acc[4] - mu) * rstd * w4b.x + b4b.x) * s4b.x;
        ob.y = ((acc[5] - mu) * rstd * w4b.y + b4b.y) * s4b.y;
        ob.z = ((acc[6] - mu) * rstd * w4b.z + b4b.z) * s4b.z;
        ob.w = ((acc[7] - mu) * rstd * w4b.w + b4b.w) * s4b.w;
        float* op = out + (size_t)row * 256 + col;
        *(float4*)op       = oa;
        *(float4*)(op + 4) = ob;
    }
}

extern "C" void kernel_launch(void* const* d_in, const int* in_sizes, int n_in,
                              void* d_out, int out_size)
{
    const float* timestamps   = (const float*)d_in[0];
    const float* freq_theta   = (const float*)d_in[1];
    const float* bias_fourier = (const float*)d_in[2];
    const float* fourier_w    = (const float*)d_in[3];
    const float* w1w          = (const float*)d_in[4];
    const float* w1b          = (const float*)d_in[5];
    const float* base_w       = (const float*)d_in[6];
    const float* spline_w     = (const float*)d_in[7];
    const float* scale_w      = (const float*)d_in[8];
    const float* ln_w         = (const float*)d_in[9];
    const float* ln_b         = (const float*)d_in[10];
    float* out = (float*)d_out;

    int nrows = in_sizes[0];   // 16384
    cudaFuncSetAttribute(tprep_kernel, cudaFuncAttributeMaxDynamicSharedMemorySize, TP_SMEM);

    prep_kernel<<<152, 256>>>(fourier_w, base_w, spline_w, freq_theta);
    tprep_kernel<<<dim3(GKNOTS / 128, 14), 512, TP_SMEM>>>(bias_fourier, w1w, w1b);
    pack_kernel<<<32, 1024>>>();
    interp_kernel<<<nrows / 32, 512>>>(timestamps, ln_w, ln_b, scale_w, out);
}